// round 6
// baseline (speedup 1.0000x reference)
#include <cuda_runtime.h>
#include <cstdint>

#define NN 50000
#define EE 600000
#define PP 100000
#define FD 128

// ---- device scratch ----
__device__ float g_agg[NN * FD];     // MEAN aggregate (division folded in)
__device__ float g_h1[NN * FD];
__device__ float g_h2[NN * FD];
__device__ int   g_cnt[NN];
__device__ int   g_cur[NN];
__device__ int   g_rowstart[NN + 1];
__device__ int   g_csr[EE];

typedef unsigned long long u64;

__device__ __forceinline__ void ffma2(u64& d, u64 a, u64 b) {
    asm("fma.rn.f32x2 %0, %1, %2, %0;" : "+l"(d) : "l"(a), "l"(b));
}
__device__ __forceinline__ void unpack2(float& lo, float& hi, u64 v) {
    asm("mov.b64 {%0, %1}, %2;" : "=f"(lo), "=f"(hi) : "l"(v));
}
__device__ __forceinline__ u64 pack2(float lo, float hi) {
    u64 r;
    asm("mov.b64 %0, {%1, %2};" : "=l"(r) : "f"(lo), "f"(hi));
    return r;
}

// ============================================================================
// CSR build: count -> scan -> fill
// ============================================================================
__global__ void count_kernel(const int* __restrict__ dst)
{
    int e = blockIdx.x * blockDim.x + threadIdx.x;
    if (e < EE) atomicAdd(&g_cnt[dst[e]], 1);
}

__global__ void __launch_bounds__(1024, 1) scan_kernel()
{
    __shared__ int wsum[32];
    __shared__ int carry;
    int tid = threadIdx.x, lane = tid & 31, w = tid >> 5;
    if (tid == 0) carry = 0;
    __syncthreads();
    for (int base = 0; base < NN; base += 1024) {
        int i = base + tid;
        int v = (i < NN) ? g_cnt[i] : 0;
        int s = v;
#pragma unroll
        for (int off = 1; off < 32; off <<= 1) {
            int t = __shfl_up_sync(0xffffffffu, s, off);
            if (lane >= off) s += t;
        }
        if (lane == 31) wsum[w] = s;
        __syncthreads();
        if (w == 0) {
            int ws = wsum[lane];
#pragma unroll
            for (int off = 1; off < 32; off <<= 1) {
                int t = __shfl_up_sync(0xffffffffu, ws, off);
                if (lane >= off) ws += t;
            }
            wsum[lane] = ws;
        }
        __syncthreads();
        int prev = (w > 0) ? wsum[w - 1] : 0;
        int incl = carry + prev + s;
        if (i < NN) g_rowstart[i + 1] = incl;
        int chunk_total = wsum[31];
        __syncthreads();
        if (tid == 0) carry += chunk_total;
        __syncthreads();
    }
    if (threadIdx.x == 0) g_rowstart[0] = 0;
}

__global__ void fill_kernel(const int* __restrict__ src,
                            const int* __restrict__ dst)
{
    int e = blockIdx.x * blockDim.x + threadIdx.x;
    if (e >= EE) return;
    int d = dst[e];
    int p = atomicAdd(&g_cur[d], 1);
    g_csr[g_rowstart[d] + p] = src[e];
}

// ============================================================================
// Aggregate: one warp per node, gather + accumulate, write MEAN.
// ============================================================================
__global__ void aggregate_kernel(const float* __restrict__ h)
{
    int gw   = (blockIdx.x * blockDim.x + threadIdx.x) >> 5;
    int lane = threadIdx.x & 31;
    if (gw >= NN) return;
    int beg = g_rowstart[gw], end = g_rowstart[gw + 1];
    const float* hp = h + lane * 4;
    float4 acc = make_float4(0.f, 0.f, 0.f, 0.f);
    int e = beg;
    for (; e + 1 < end; e += 2) {
        int s0 = g_csr[e], s1 = g_csr[e + 1];
        float4 v0 = *(const float4*)(hp + s0 * FD);
        float4 v1 = *(const float4*)(hp + s1 * FD);
        acc.x += v0.x + v1.x; acc.y += v0.y + v1.y;
        acc.z += v0.z + v1.z; acc.w += v0.w + v1.w;
    }
    if (e < end) {
        int s0 = g_csr[e];
        float4 v0 = *(const float4*)(hp + s0 * FD);
        acc.x += v0.x; acc.y += v0.y; acc.z += v0.z; acc.w += v0.w;
    }
    float rd = 1.0f / fmaxf((float)(end - beg), 1.0f);
    acc.x *= rd; acc.y *= rd; acc.z *= rd; acc.w *= rd;
    *(float4*)(g_agg + gw * FD + lane * 4) = acc;
}

// ============================================================================
// SAGE linear: mov-free k-interleaved FFMA2, 8 rows x 128 cols per warp.
// smem: packed weight pairs [128][128] u64 (128KB) + stage [16][8][128] (64KB)
// acc[r][c] holds (sum over even k, sum over odd k) for column lane*4+c.
// ============================================================================
template <bool RELU>
__global__ void __launch_bounds__(512, 1)
sage_linear_kernel(const float* __restrict__ x,
                   const float* __restrict__ Ws,
                   const float* __restrict__ Wn,
                   const float* __restrict__ b,
                   float* __restrict__ out)
{
    extern __shared__ float sm[];
    u64*   smWp  = (u64*)sm;           // [128 pairs][128 cols]
    float* stage = sm + 2 * 128 * 128; // [16][8][128]

    int tid  = threadIdx.x;
    int lane = tid & 31;
    int warp = tid >> 5;

    // packed weights: smWp[pt*128+c] = (W[2pt][c], W[2pt+1][c]), K = [Ws; Wn]
    for (int i = tid; i < 128 * 128; i += blockDim.x) {
        int pt = i >> 7, c = i & 127;
        int k0 = 2 * pt;
        float w0, w1;
        if (k0 < 128) { w0 = Ws[k0 * 128 + c];         w1 = Ws[(k0 + 1) * 128 + c]; }
        else          { w0 = Wn[(k0 - 128) * 128 + c]; w1 = Wn[(k0 - 127) * 128 + c]; }
        smWp[i] = pack2(w0, w1);
    }
    __syncthreads();

    float4 bias = *(const float4*)(b + lane * 4);
    float* myStage = stage + warp * (8 * 128);

    for (int base = blockIdx.x * 128 + warp * 8; base < NN;
         base += gridDim.x * 128) {

        u64 acc[8][4];
#pragma unroll
        for (int r = 0; r < 8; r++)
#pragma unroll
            for (int c = 0; c < 4; c++) acc[r][c] = 0ull;

#pragma unroll 1
        for (int h = 0; h < 2; h++) {
            // stage 8 rows of this K-half (warp-local)
#pragma unroll
            for (int r = 0; r < 8; r++) {
                int row = base + r;
                float4 v = make_float4(0.f, 0.f, 0.f, 0.f);
                if (row < NN) {
                    const float* p = (h == 0) ? x : (const float*)g_agg;
                    v = *(const float4*)(p + row * FD + lane * 4);
                }
                *(float4*)(myStage + r * 128 + lane * 4) = v;
            }
            __syncwarp();

            const u64* wrow = smWp + h * 64 * 128 + lane * 4;
#pragma unroll 1
            for (int t = 0; t < 64; t += 2) {
                ulonglong2 wa0 = *(const ulonglong2*)(wrow + t * 128);
                ulonglong2 wa1 = *(const ulonglong2*)(wrow + t * 128 + 2);
                ulonglong2 wb0 = *(const ulonglong2*)(wrow + (t + 1) * 128);
                ulonglong2 wb1 = *(const ulonglong2*)(wrow + (t + 1) * 128 + 2);
#pragma unroll
                for (int r = 0; r < 8; r++) {
                    ulonglong2 xv = *(const ulonglong2*)(myStage + r * 128 + t * 2);
                    ffma2(acc[r][0], xv.x, wa0.x);
                    ffma2(acc[r][1], xv.x, wa0.y);
                    ffma2(acc[r][2], xv.x, wa1.x);
                    ffma2(acc[r][3], xv.x, wa1.y);
                    ffma2(acc[r][0], xv.y, wb0.x);
                    ffma2(acc[r][1], xv.y, wb0.y);
                    ffma2(acc[r][2], xv.y, wb1.x);
                    ffma2(acc[r][3], xv.y, wb1.y);
                }
            }
            __syncwarp();
        }

#pragma unroll
        for (int r = 0; r < 8; r++) {
            int row = base + r;
            if (row < NN) {
                float o[4];
#pragma unroll
                for (int c = 0; c < 4; c++) {
                    float lo, hi;
                    unpack2(lo, hi, acc[r][c]);
                    o[c] = lo + hi;
                }
                float4 ov;
                ov.x = o[0] + bias.x; ov.y = o[1] + bias.y;
                ov.z = o[2] + bias.z; ov.w = o[3] + bias.w;
                if (RELU) {
                    ov.x = fmaxf(ov.x, 0.f); ov.y = fmaxf(ov.y, 0.f);
                    ov.z = fmaxf(ov.z, 0.f); ov.w = fmaxf(ov.w, 0.f);
                }
                *(float4*)(out + row * FD + lane * 4) = ov;
            }
        }
    }
}

// ============================================================================
// Fused decoder: mov-free k-interleaved FFMA2, 8 rows x 128 cols per warp.
// smem: W1p (64KB) + W2p (64KB) packed pairs + stage [16][8][128] (64KB)
// ============================================================================
__global__ void __launch_bounds__(512, 1)
decoder_kernel(const float* __restrict__ h,
               const int* __restrict__ ps, const int* __restrict__ pd,
               const int* __restrict__ ns, const int* __restrict__ nd,
               const float* __restrict__ Wd1, const float* __restrict__ bd1,
               const float* __restrict__ Wd2, const float* __restrict__ bd2,
               const float* __restrict__ Wd3, const float* __restrict__ bd3,
               float* __restrict__ out)
{
    extern __shared__ float sm[];
    u64*   smW1p = (u64*)sm;              // [64 pairs][128 cols]
    u64*   smW2p = (u64*)sm + 64 * 128;   // [64 pairs][128 cols]
    float* stage = sm + 2 * 128 * 128;    // [16][8][128]

    int tid  = threadIdx.x;
    int lane = tid & 31;
    int warp = tid >> 5;

    for (int i = tid; i < 64 * 128; i += blockDim.x) {
        int pt = i >> 7, c = i & 127;
        smW1p[i] = pack2(Wd1[2 * pt * 128 + c], Wd1[(2 * pt + 1) * 128 + c]);
        smW2p[i] = pack2(Wd2[2 * pt * 128 + c], Wd2[(2 * pt + 1) * 128 + c]);
    }
    __syncthreads();

    float4 b1v = *(const float4*)(bd1 + lane * 4);
    float4 b2v = *(const float4*)(bd2 + lane * 4);
    float4 w3v = *(const float4*)(Wd3 + lane * 4);
    float  b3  = bd3[0];

    float* myStage = stage + warp * (8 * 128);
    const u64* w1row = smW1p + lane * 4;
    const u64* w2row = smW2p + lane * 4;
    const int total = 2 * PP;

    for (int base = blockIdx.x * 128 + warp * 8; base < total;
         base += gridDim.x * 128) {
        // ---- stage z = h[s] * h[d] ----
#pragma unroll
        for (int r = 0; r < 8; r++) {
            int p = base + r;
            float4 z = make_float4(0.f, 0.f, 0.f, 0.f);
            if (p < total) {
                int s, d;
                if (p < PP) { s = ps[p]; d = pd[p]; }
                else        { s = ns[p - PP]; d = nd[p - PP]; }
                float4 a = *(const float4*)(h + s * FD + lane * 4);
                float4 c = *(const float4*)(h + d * FD + lane * 4);
                z.x = a.x * c.x; z.y = a.y * c.y;
                z.z = a.z * c.z; z.w = a.w * c.w;
            }
            *(float4*)(myStage + r * 128 + lane * 4) = z;
        }
        __syncwarp();

        u64 acc[8][4];

        // ---- GEMV 1 ----
#pragma unroll
        for (int r = 0; r < 8; r++)
#pragma unroll
            for (int c = 0; c < 4; c++) acc[r][c] = 0ull;
#pragma unroll 1
        for (int t = 0; t < 64; t += 2) {
            ulonglong2 wa0 = *(const ulonglong2*)(w1row + t * 128);
            ulonglong2 wa1 = *(const ulonglong2*)(w1row + t * 128 + 2);
            ulonglong2 wb0 = *(const ulonglong2*)(w1row + (t + 1) * 128);
            ulonglong2 wb1 = *(const ulonglong2*)(w1row + (t + 1) * 128 + 2);
#pragma unroll
            for (int r = 0; r < 8; r++) {
                ulonglong2 xv = *(const ulonglong2*)(myStage + r * 128 + t * 2);
                ffma2(acc[r][0], xv.x, wa0.x);
                ffma2(acc[r][1], xv.x, wa0.y);
                ffma2(acc[r][2], xv.x, wa1.x);
                ffma2(acc[r][3], xv.x, wa1.y);
                ffma2(acc[r][0], xv.y, wb0.x);
                ffma2(acc[r][1], xv.y, wb0.y);
                ffma2(acc[r][2], xv.y, wb1.x);
                ffma2(acc[r][3], xv.y, wb1.y);
            }
        }
        __syncwarp();

        // ---- t1 = relu(sum + b1) -> restage ----
#pragma unroll
        for (int r = 0; r < 8; r++) {
            float o[4];
#pragma unroll
            for (int c = 0; c < 4; c++) {
                float lo, hi;
                unpack2(lo, hi, acc[r][c]);
                o[c] = lo + hi;
            }
            float4 tq;
            tq.x = fmaxf(o[0] + b1v.x, 0.f);
            tq.y = fmaxf(o[1] + b1v.y, 0.f);
            tq.z = fmaxf(o[2] + b1v.z, 0.f);
            tq.w = fmaxf(o[3] + b1v.w, 0.f);
            *(float4*)(myStage + r * 128 + lane * 4) = tq;
        }
        __syncwarp();

        // ---- GEMV 2 ----
#pragma unroll
        for (int r = 0; r < 8; r++)
#pragma unroll
            for (int c = 0; c < 4; c++) acc[r][c] = 0ull;
#pragma unroll 1
        for (int t = 0; t < 64; t += 2) {
            ulonglong2 wa0 = *(const ulonglong2*)(w2row + t * 128);
            ulonglong2 wa1 = *(const ulonglong2*)(w2row + t * 128 + 2);
            ulonglong2 wb0 = *(const ulonglong2*)(w2row + (t + 1) * 128);
            ulonglong2 wb1 = *(const ulonglong2*)(w2row + (t + 1) * 128 + 2);
#pragma unroll
            for (int r = 0; r < 8; r++) {
                ulonglong2 xv = *(const ulonglong2*)(myStage + r * 128 + t * 2);
                ffma2(acc[r][0], xv.x, wa0.x);
                ffma2(acc[r][1], xv.x, wa0.y);
                ffma2(acc[r][2], xv.x, wa1.x);
                ffma2(acc[r][3], xv.x, wa1.y);
                ffma2(acc[r][0], xv.y, wb0.x);
                ffma2(acc[r][1], xv.y, wb0.y);
                ffma2(acc[r][2], xv.y, wb1.x);
                ffma2(acc[r][3], xv.y, wb1.y);
            }
        }

        // ---- out = relu(sum + b2) . Wd3 + bd3 ----
#pragma unroll
        for (int r = 0; r < 8; r++) {
            float o[4];
#pragma unroll
            for (int c = 0; c < 4; c++) {
                float lo, hi;
                unpack2(lo, hi, acc[r][c]);
                o[c] = lo + hi;
            }
            float t0 = fmaxf(o[0] + b2v.x, 0.f);
            float t1 = fmaxf(o[1] + b2v.y, 0.f);
            float t2 = fmaxf(o[2] + b2v.z, 0.f);
            float t3 = fmaxf(o[3] + b2v.w, 0.f);
            float partial = t0 * w3v.x + t1 * w3v.y + t2 * w3v.z + t3 * w3v.w;
#pragma unroll
            for (int off = 16; off > 0; off >>= 1)
                partial += __shfl_xor_sync(0xffffffffu, partial, off);
            int p = base + r;
            if (lane == 0 && p < total) out[p] = partial + b3;
        }
        __syncwarp();
    }
}

// ============================================================================
// launch
// ============================================================================
extern "C" void kernel_launch(void* const* d_in, const int* in_sizes, int n_in,
                              void* d_out, int out_size)
{
    const float* x    = (const float*)d_in[0];
    const int*   esrc = (const int*)  d_in[1];
    const int*   edst = (const int*)  d_in[2];
    const int*   ps   = (const int*)  d_in[3];
    const int*   pd   = (const int*)  d_in[4];
    const int*   ns   = (const int*)  d_in[5];
    const int*   nd   = (const int*)  d_in[6];
    const float* Ws1  = (const float*)d_in[7];
    const float* Wn1  = (const float*)d_in[8];
    const float* b1   = (const float*)d_in[9];
    const float* Ws2  = (const float*)d_in[10];
    const float* Wn2  = (const float*)d_in[11];
    const float* b2   = (const float*)d_in[12];
    const float* Wd1  = (const float*)d_in[13];
    const float* bd1  = (const float*)d_in[14];
    const float* Wd2  = (const float*)d_in[15];
    const float* bd2  = (const float*)d_in[16];
    const float* Wd3  = (const float*)d_in[17];
    const float* bd3  = (const float*)d_in[18];
    float* out = (float*)d_out;

    void *cntPtr, *curPtr, *h1Ptr, *h2Ptr;
    cudaGetSymbolAddress(&cntPtr, g_cnt);
    cudaGetSymbolAddress(&curPtr, g_cur);
    cudaGetSymbolAddress(&h1Ptr,  g_h1);
    cudaGetSymbolAddress(&h2Ptr,  g_h2);

    int nsm = 148;
    cudaDeviceGetAttribute(&nsm, cudaDevAttrMultiProcessorCount, 0);

    const int SAGE_SMEM = 2 * 128 * 128 * 4 + 16 * 8 * 128 * 4;   // 196608 B
    const int DEC_SMEM  = 2 * 128 * 128 * 4 + 16 * 8 * 128 * 4;   // 196608 B
    cudaFuncSetAttribute(sage_linear_kernel<true>,
                         cudaFuncAttributeMaxDynamicSharedMemorySize, SAGE_SMEM);
    cudaFuncSetAttribute(sage_linear_kernel<false>,
                         cudaFuncAttributeMaxDynamicSharedMemorySize, SAGE_SMEM);
    cudaFuncSetAttribute(decoder_kernel,
                         cudaFuncAttributeMaxDynamicSharedMemorySize, DEC_SMEM);

    // ---- CSR build ----
    cudaMemsetAsync(cntPtr, 0, sizeof(int) * NN, 0);
    cudaMemsetAsync(curPtr, 0, sizeof(int) * NN, 0);
    count_kernel<<<(EE + 255) / 256, 256>>>(edst);
    scan_kernel<<<1, 1024>>>();
    fill_kernel<<<(EE + 255) / 256, 256>>>(esrc, edst);

    int ablocks = (NN * 32 + 255) / 256;

    // ---- layer 1 ----
    aggregate_kernel<<<ablocks, 256>>>(x);
    sage_linear_kernel<true><<<nsm, 512, SAGE_SMEM>>>(x, Ws1, Wn1, b1,
                                                      (float*)h1Ptr);
    // ---- layer 2 ----
    aggregate_kernel<<<ablocks, 256>>>((const float*)h1Ptr);
    sage_linear_kernel<false><<<nsm, 512, SAGE_SMEM>>>((const float*)h1Ptr,
                                                       Ws2, Wn2, b2,
                                                       (float*)h2Ptr);
    // ---- decoder ----
    decoder_kernel<<<nsm, 512, DEC_SMEM>>>((const float*)h2Ptr,
                                           ps, pd, ns, nd,
                                           Wd1, bd1, Wd2, bd2, Wd3, bd3, out);
}

// round 7
// speedup vs baseline: 1.1834x; 1.1834x over previous
#include <cuda_runtime.h>
#include <cstdint>

#define NN 50000
#define EE 600000
#define PP 100000
#define FD 128

// ---- device scratch ----
__device__ float g_agg[NN * FD];     // MEAN aggregate (division folded in)
__device__ float g_h1[NN * FD];
__device__ float g_h2[NN * FD];
__device__ int   g_cnt[NN];
__device__ int   g_cur[NN];
__device__ int   g_rowstart[NN + 1];
__device__ int   g_csr[EE];

typedef unsigned long long u64;

__device__ __forceinline__ void ffma2(u64& d, u64 a, u64 b) {
    asm("fma.rn.f32x2 %0, %1, %2, %0;" : "+l"(d) : "l"(a), "l"(b));
}
__device__ __forceinline__ void unpack2(float& lo, float& hi, u64 v) {
    asm("mov.b64 {%0, %1}, %2;" : "=f"(lo), "=f"(hi) : "l"(v));
}
__device__ __forceinline__ u64 pack_dup(float a) {
    u64 r;
    asm("mov.b64 %0, {%1, %1};" : "=l"(r) : "f"(a));
    return r;
}

// ============================================================================
// CSR build: count -> scan -> fill
// ============================================================================
__global__ void count_kernel(const int* __restrict__ dst)
{
    int e = blockIdx.x * blockDim.x + threadIdx.x;
    if (e < EE) atomicAdd(&g_cnt[dst[e]], 1);
}

__global__ void __launch_bounds__(1024, 1) scan_kernel()
{
    __shared__ int wsum[32];
    __shared__ int carry;
    int tid = threadIdx.x, lane = tid & 31, w = tid >> 5;
    if (tid == 0) carry = 0;
    __syncthreads();
    for (int base = 0; base < NN; base += 1024) {
        int i = base + tid;
        int v = (i < NN) ? g_cnt[i] : 0;
        int s = v;
#pragma unroll
        for (int off = 1; off < 32; off <<= 1) {
            int t = __shfl_up_sync(0xffffffffu, s, off);
            if (lane >= off) s += t;
        }
        if (lane == 31) wsum[w] = s;
        __syncthreads();
        if (w == 0) {
            int ws = wsum[lane];
#pragma unroll
            for (int off = 1; off < 32; off <<= 1) {
                int t = __shfl_up_sync(0xffffffffu, ws, off);
                if (lane >= off) ws += t;
            }
            wsum[lane] = ws;
        }
        __syncthreads();
        int prev = (w > 0) ? wsum[w - 1] : 0;
        int incl = carry + prev + s;
        if (i < NN) g_rowstart[i + 1] = incl;
        int chunk_total = wsum[31];
        __syncthreads();
        if (tid == 0) carry += chunk_total;
        __syncthreads();
    }
    if (threadIdx.x == 0) g_rowstart[0] = 0;
}

__global__ void fill_kernel(const int* __restrict__ src,
                            const int* __restrict__ dst)
{
    int e = blockIdx.x * blockDim.x + threadIdx.x;
    if (e >= EE) return;
    int d = dst[e];
    int p = atomicAdd(&g_cur[d], 1);
    g_csr[g_rowstart[d] + p] = src[e];
}

// ============================================================================
// Aggregate: one warp per node; 4 neighbor rows in flight (MLP=4),
// two independent accumulator chains.
// ============================================================================
__global__ void aggregate_kernel(const float* __restrict__ h)
{
    int gw   = (blockIdx.x * blockDim.x + threadIdx.x) >> 5;
    int lane = threadIdx.x & 31;
    if (gw >= NN) return;
    int beg = __ldg(&g_rowstart[gw]), end = __ldg(&g_rowstart[gw + 1]);
    const float* hp = h + lane * 4;
    float4 accA = make_float4(0.f, 0.f, 0.f, 0.f);
    float4 accB = make_float4(0.f, 0.f, 0.f, 0.f);
    int e = beg;
    for (; e + 3 < end; e += 4) {
        int s0 = __ldg(&g_csr[e]);
        int s1 = __ldg(&g_csr[e + 1]);
        int s2 = __ldg(&g_csr[e + 2]);
        int s3 = __ldg(&g_csr[e + 3]);
        float4 v0 = __ldg((const float4*)(hp + s0 * FD));
        float4 v1 = __ldg((const float4*)(hp + s1 * FD));
        float4 v2 = __ldg((const float4*)(hp + s2 * FD));
        float4 v3 = __ldg((const float4*)(hp + s3 * FD));
        accA.x += v0.x + v1.x; accA.y += v0.y + v1.y;
        accA.z += v0.z + v1.z; accA.w += v0.w + v1.w;
        accB.x += v2.x + v3.x; accB.y += v2.y + v3.y;
        accB.z += v2.z + v3.z; accB.w += v2.w + v3.w;
    }
    for (; e < end; e++) {
        int s0 = __ldg(&g_csr[e]);
        float4 v0 = __ldg((const float4*)(hp + s0 * FD));
        accA.x += v0.x; accA.y += v0.y; accA.z += v0.z; accA.w += v0.w;
    }
    float rd = 1.0f / fmaxf((float)(end - beg), 1.0f);
    float4 acc;
    acc.x = (accA.x + accB.x) * rd;
    acc.y = (accA.y + accB.y) * rd;
    acc.z = (accA.z + accB.z) * rd;
    acc.w = (accA.w + accB.w) * rd;
    *(float4*)(g_agg + gw * FD + lane * 4) = acc;
}

// ============================================================================
// SAGE linear (R5 form, proven): FFMA2, 8 rows x 128 cols per warp,
// K staged in two halves. smem: weights [256][128] fp32 + stage [16][8][128].
// ============================================================================
template <bool RELU>
__global__ void __launch_bounds__(512, 1)
sage_linear_kernel(const float* __restrict__ x,
                   const float* __restrict__ Ws,
                   const float* __restrict__ Wn,
                   const float* __restrict__ b,
                   float* __restrict__ out)
{
    extern __shared__ float sm[];
    float* smW   = sm;                 // [256][128]
    float* stage = sm + 256 * 128;     // [16][8][128]

    int tid  = threadIdx.x;
    int lane = tid & 31;
    int warp = tid >> 5;

    for (int i = tid; i < (128 * 128) / 4; i += blockDim.x) {
        ((float4*)smW)[i]               = ((const float4*)Ws)[i];
        ((float4*)(smW + 128 * 128))[i] = ((const float4*)Wn)[i];
    }
    __syncthreads();

    float4 bias = *(const float4*)(b + lane * 4);
    float* myStage = stage + warp * (8 * 128);

    for (int base = blockIdx.x * 128 + warp * 8; base < NN;
         base += gridDim.x * 128) {

        u64 acc[8][2];
#pragma unroll
        for (int r = 0; r < 8; r++) { acc[r][0] = 0ull; acc[r][1] = 0ull; }

#pragma unroll 1
        for (int h = 0; h < 2; h++) {
#pragma unroll
            for (int r = 0; r < 8; r++) {
                int row = base + r;
                float4 v = make_float4(0.f, 0.f, 0.f, 0.f);
                if (row < NN) {
                    const float* p = (h == 0) ? x : (const float*)g_agg;
                    v = *(const float4*)(p + row * FD + lane * 4);
                }
                *(float4*)(myStage + r * 128 + lane * 4) = v;
            }
            __syncwarp();

            const float* wbase = smW + h * 128 * 128;
#pragma unroll 1
            for (int k = 0; k < 128; k += 4) {
                float4 xq[8];
#pragma unroll
                for (int r = 0; r < 8; r++)
                    xq[r] = *(const float4*)(myStage + r * 128 + k);
#pragma unroll
                for (int kk = 0; kk < 4; kk++) {
                    ulonglong2 w = *(const ulonglong2*)(wbase + (k + kk) * 128 + lane * 4);
#pragma unroll
                    for (int r = 0; r < 8; r++) {
                        float xs = (kk == 0) ? xq[r].x : (kk == 1) ? xq[r].y
                                 : (kk == 2) ? xq[r].z : xq[r].w;
                        u64 xx = pack_dup(xs);
                        ffma2(acc[r][0], xx, w.x);
                        ffma2(acc[r][1], xx, w.y);
                    }
                }
            }
            __syncwarp();
        }

#pragma unroll
        for (int r = 0; r < 8; r++) {
            int row = base + r;
            if (row < NN) {
                float4 o;
                unpack2(o.x, o.y, acc[r][0]);
                unpack2(o.z, o.w, acc[r][1]);
                o.x += bias.x; o.y += bias.y; o.z += bias.z; o.w += bias.w;
                if (RELU) {
                    o.x = fmaxf(o.x, 0.f); o.y = fmaxf(o.y, 0.f);
                    o.z = fmaxf(o.z, 0.f); o.w = fmaxf(o.w, 0.f);
                }
                *(float4*)(out + row * FD + lane * 4) = o;
            }
        }
    }
}

// ============================================================================
// Fused decoder (R5 form, proven): FFMA2, 8 rows x 128 cols per warp.
// ============================================================================
__global__ void __launch_bounds__(512, 1)
decoder_kernel(const float* __restrict__ h,
               const int* __restrict__ ps, const int* __restrict__ pd,
               const int* __restrict__ ns, const int* __restrict__ nd,
               const float* __restrict__ Wd1, const float* __restrict__ bd1,
               const float* __restrict__ Wd2, const float* __restrict__ bd2,
               const float* __restrict__ Wd3, const float* __restrict__ bd3,
               float* __restrict__ out)
{
    extern __shared__ float sm[];
    float* smW1  = sm;                 // [128][128]
    float* smW2  = sm + 128 * 128;     // [128][128]
    float* stage = sm + 2 * 128 * 128; // [16][8][128]

    int tid  = threadIdx.x;
    int lane = tid & 31;
    int warp = tid >> 5;

    for (int i = tid; i < (128 * 128) / 4; i += blockDim.x) {
        ((float4*)smW1)[i] = ((const float4*)Wd1)[i];
        ((float4*)smW2)[i] = ((const float4*)Wd2)[i];
    }
    __syncthreads();

    float4 b1v = *(const float4*)(bd1 + lane * 4);
    float4 b2v = *(const float4*)(bd2 + lane * 4);
    float4 w3v = *(const float4*)(Wd3 + lane * 4);
    float  b3  = bd3[0];

    float* myStage = stage + warp * (8 * 128);
    const int total = 2 * PP;

    for (int base = blockIdx.x * 128 + warp * 8; base < total;
         base += gridDim.x * 128) {
        // ---- stage z = h[s] * h[d] ----
#pragma unroll
        for (int r = 0; r < 8; r++) {
            int p = base + r;
            float4 z = make_float4(0.f, 0.f, 0.f, 0.f);
            if (p < total) {
                int s, d;
                if (p < PP) { s = ps[p]; d = pd[p]; }
                else        { s = ns[p - PP]; d = nd[p - PP]; }
                float4 a = *(const float4*)(h + s * FD + lane * 4);
                float4 c = *(const float4*)(h + d * FD + lane * 4);
                z.x = a.x * c.x; z.y = a.y * c.y;
                z.z = a.z * c.z; z.w = a.w * c.w;
            }
            *(float4*)(myStage + r * 128 + lane * 4) = z;
        }
        __syncwarp();

        u64 acc[8][2];

        // ---- GEMV 1 ----
#pragma unroll
        for (int r = 0; r < 8; r++) { acc[r][0] = 0ull; acc[r][1] = 0ull; }
#pragma unroll 1
        for (int k = 0; k < 128; k += 4) {
            float4 zq[8];
#pragma unroll
            for (int r = 0; r < 8; r++)
                zq[r] = *(const float4*)(myStage + r * 128 + k);
#pragma unroll
            for (int kk = 0; kk < 4; kk++) {
                ulonglong2 w = *(const ulonglong2*)(smW1 + (k + kk) * 128 + lane * 4);
#pragma unroll
                for (int r = 0; r < 8; r++) {
                    float zs = (kk == 0) ? zq[r].x : (kk == 1) ? zq[r].y
                             : (kk == 2) ? zq[r].z : zq[r].w;
                    u64 zz = pack_dup(zs);
                    ffma2(acc[r][0], zz, w.x);
                    ffma2(acc[r][1], zz, w.y);
                }
            }
        }
        __syncwarp();

        // ---- t1 = relu(acc + b1) -> restage (warp-local) ----
#pragma unroll
        for (int r = 0; r < 8; r++) {
            float lo0, hi0, lo1, hi1;
            unpack2(lo0, hi0, acc[r][0]);
            unpack2(lo1, hi1, acc[r][1]);
            float4 tq;
            tq.x = fmaxf(lo0 + b1v.x, 0.f);
            tq.y = fmaxf(hi0 + b1v.y, 0.f);
            tq.z = fmaxf(lo1 + b1v.z, 0.f);
            tq.w = fmaxf(hi1 + b1v.w, 0.f);
            *(float4*)(myStage + r * 128 + lane * 4) = tq;
        }
        __syncwarp();

        // ---- GEMV 2 ----
#pragma unroll
        for (int r = 0; r < 8; r++) { acc[r][0] = 0ull; acc[r][1] = 0ull; }
#pragma unroll 1
        for (int k = 0; k < 128; k += 4) {
            float4 zq[8];
#pragma unroll
            for (int r = 0; r < 8; r++)
                zq[r] = *(const float4*)(myStage + r * 128 + k);
#pragma unroll
            for (int kk = 0; kk < 4; kk++) {
                ulonglong2 w = *(const ulonglong2*)(smW2 + (k + kk) * 128 + lane * 4);
#pragma unroll
                for (int r = 0; r < 8; r++) {
                    float zs = (kk == 0) ? zq[r].x : (kk == 1) ? zq[r].y
                             : (kk == 2) ? zq[r].z : zq[r].w;
                    u64 zz = pack_dup(zs);
                    ffma2(acc[r][0], zz, w.x);
                    ffma2(acc[r][1], zz, w.y);
                }
            }
        }

        // ---- out = relu(acc + b2) . Wd3 + bd3 ----
#pragma unroll
        for (int r = 0; r < 8; r++) {
            float t0, t1, t2, t3;
            unpack2(t0, t1, acc[r][0]);
            unpack2(t2, t3, acc[r][1]);
            t0 = fmaxf(t0 + b2v.x, 0.f);
            t1 = fmaxf(t1 + b2v.y, 0.f);
            t2 = fmaxf(t2 + b2v.z, 0.f);
            t3 = fmaxf(t3 + b2v.w, 0.f);
            float partial = t0 * w3v.x + t1 * w3v.y + t2 * w3v.z + t3 * w3v.w;
#pragma unroll
            for (int off = 16; off > 0; off >>= 1)
                partial += __shfl_xor_sync(0xffffffffu, partial, off);
            int p = base + r;
            if (lane == 0 && p < total) out[p] = partial + b3;
        }
        __syncwarp();
    }
}

// ============================================================================
// launch
// ============================================================================
extern "C" void kernel_launch(void* const* d_in, const int* in_sizes, int n_in,
                              void* d_out, int out_size)
{
    const float* x    = (const float*)d_in[0];
    const int*   esrc = (const int*)  d_in[1];
    const int*   edst = (const int*)  d_in[2];
    const int*   ps   = (const int*)  d_in[3];
    const int*   pd   = (const int*)  d_in[4];
    const int*   ns   = (const int*)  d_in[5];
    const int*   nd   = (const int*)  d_in[6];
    const float* Ws1  = (const float*)d_in[7];
    const float* Wn1  = (const float*)d_in[8];
    const float* b1   = (const float*)d_in[9];
    const float* Ws2  = (const float*)d_in[10];
    const float* Wn2  = (const float*)d_in[11];
    const float* b2   = (const float*)d_in[12];
    const float* Wd1  = (const float*)d_in[13];
    const float* bd1  = (const float*)d_in[14];
    const float* Wd2  = (const float*)d_in[15];
    const float* bd2  = (const float*)d_in[16];
    const float* Wd3  = (const float*)d_in[17];
    const float* bd3  = (const float*)d_in[18];
    float* out = (float*)d_out;

    void *cntPtr, *curPtr, *h1Ptr, *h2Ptr;
    cudaGetSymbolAddress(&cntPtr, g_cnt);
    cudaGetSymbolAddress(&curPtr, g_cur);
    cudaGetSymbolAddress(&h1Ptr,  g_h1);
    cudaGetSymbolAddress(&h2Ptr,  g_h2);

    int nsm = 148;
    cudaDeviceGetAttribute(&nsm, cudaDevAttrMultiProcessorCount, 0);

    const int SAGE_SMEM = 256 * 128 * 4 + 16 * 8 * 128 * 4;       // 196608 B
    const int DEC_SMEM  = 2 * 128 * 128 * 4 + 16 * 8 * 128 * 4;   // 196608 B
    cudaFuncSetAttribute(sage_linear_kernel<true>,
                         cudaFuncAttributeMaxDynamicSharedMemorySize, SAGE_SMEM);
    cudaFuncSetAttribute(sage_linear_kernel<false>,
                         cudaFuncAttributeMaxDynamicSharedMemorySize, SAGE_SMEM);
    cudaFuncSetAttribute(decoder_kernel,
                         cudaFuncAttributeMaxDynamicSharedMemorySize, DEC_SMEM);

    // ---- CSR build ----
    cudaMemsetAsync(cntPtr, 0, sizeof(int) * NN, 0);
    cudaMemsetAsync(curPtr, 0, sizeof(int) * NN, 0);
    count_kernel<<<(EE + 255) / 256, 256>>>(edst);
    scan_kernel<<<1, 1024>>>();
    fill_kernel<<<(EE + 255) / 256, 256>>>(esrc, edst);

    int ablocks = (NN * 32 + 255) / 256;

    // ---- layer 1 ----
    aggregate_kernel<<<ablocks, 256>>>(x);
    sage_linear_kernel<true><<<nsm, 512, SAGE_SMEM>>>(x, Ws1, Wn1, b1,
                                                      (float*)h1Ptr);
    // ---- layer 2 ----
    aggregate_kernel<<<ablocks, 256>>>((const float*)h1Ptr);
    sage_linear_kernel<false><<<nsm, 512, SAGE_SMEM>>>((const float*)h1Ptr,
                                                       Ws2, Wn2, b2,
                                                       (float*)h2Ptr);
    // ---- decoder ----
    decoder_kernel<<<nsm, 512, DEC_SMEM>>>((const float*)h2Ptr,
                                           ps, pd, ns, nd,
                                           Wd1, bd1, Wd2, bd2, Wd3, bd3, out);
}

// round 8
// speedup vs baseline: 1.2597x; 1.0644x over previous
#include <cuda_runtime.h>
#include <cstdint>

#define NN 50000
#define EE 600000
#define PP 100000
#define FD 128

// ---- device scratch ----
__device__ float g_agg[NN * FD];     // MEAN aggregate (division folded in)
__device__ float g_h1[NN * FD];
__device__ float g_h2[NN * FD];
__device__ int   g_cnt[NN];
__device__ int   g_cur[NN];
__device__ int   g_rowstart[NN + 1];
__device__ int   g_csr[EE];

typedef unsigned long long u64;

__device__ __forceinline__ void ffma2(u64& d, u64 a, u64 b) {
    asm("fma.rn.f32x2 %0, %1, %2, %0;" : "+l"(d) : "l"(a), "l"(b));
}
__device__ __forceinline__ void unpack2(float& lo, float& hi, u64 v) {
    asm("mov.b64 {%0, %1}, %2;" : "=f"(lo), "=f"(hi) : "l"(v));
}
__device__ __forceinline__ u64 pack_dup(float a) {
    u64 r;
    asm("mov.b64 %0, {%1, %1};" : "=l"(r) : "f"(a));
    return r;
}

// ============================================================================
// CSR build: count -> scan -> fill
// ============================================================================
__global__ void count_kernel(const int* __restrict__ dst)
{
    int e = blockIdx.x * blockDim.x + threadIdx.x;
    if (e < EE) atomicAdd(&g_cnt[dst[e]], 1);
}

__global__ void __launch_bounds__(1024, 1) scan_kernel()
{
    __shared__ int wsum[32];
    __shared__ int carry;
    int tid = threadIdx.x, lane = tid & 31, w = tid >> 5;
    if (tid == 0) carry = 0;
    __syncthreads();
    for (int base = 0; base < NN; base += 1024) {
        int i = base + tid;
        int v = (i < NN) ? g_cnt[i] : 0;
        int s = v;
#pragma unroll
        for (int off = 1; off < 32; off <<= 1) {
            int t = __shfl_up_sync(0xffffffffu, s, off);
            if (lane >= off) s += t;
        }
        if (lane == 31) wsum[w] = s;
        __syncthreads();
        if (w == 0) {
            int ws = wsum[lane];
#pragma unroll
            for (int off = 1; off < 32; off <<= 1) {
                int t = __shfl_up_sync(0xffffffffu, ws, off);
                if (lane >= off) ws += t;
            }
            wsum[lane] = ws;
        }
        __syncthreads();
        int prev = (w > 0) ? wsum[w - 1] : 0;
        int incl = carry + prev + s;
        if (i < NN) g_rowstart[i + 1] = incl;
        int chunk_total = wsum[31];
        __syncthreads();
        if (tid == 0) carry += chunk_total;
        __syncthreads();
    }
    if (threadIdx.x == 0) g_rowstart[0] = 0;
}

__global__ void fill_kernel(const int* __restrict__ src,
                            const int* __restrict__ dst)
{
    int e = blockIdx.x * blockDim.x + threadIdx.x;
    if (e >= EE) return;
    int d = dst[e];
    int p = atomicAdd(&g_cur[d], 1);
    g_csr[g_rowstart[d] + p] = src[e];
}

// ============================================================================
// Aggregate (R5 exact): one warp per node, gather + accumulate, write MEAN.
// ============================================================================
__global__ void aggregate_kernel(const float* __restrict__ h)
{
    int gw   = (blockIdx.x * blockDim.x + threadIdx.x) >> 5;
    int lane = threadIdx.x & 31;
    if (gw >= NN) return;
    int beg = g_rowstart[gw], end = g_rowstart[gw + 1];
    const float* hp = h + lane * 4;
    float4 acc = make_float4(0.f, 0.f, 0.f, 0.f);
    int e = beg;
    for (; e + 1 < end; e += 2) {
        int s0 = g_csr[e], s1 = g_csr[e + 1];
        float4 v0 = *(const float4*)(hp + s0 * FD);
        float4 v1 = *(const float4*)(hp + s1 * FD);
        acc.x += v0.x + v1.x; acc.y += v0.y + v1.y;
        acc.z += v0.z + v1.z; acc.w += v0.w + v1.w;
    }
    if (e < end) {
        int s0 = g_csr[e];
        float4 v0 = *(const float4*)(hp + s0 * FD);
        acc.x += v0.x; acc.y += v0.y; acc.z += v0.z; acc.w += v0.w;
    }
    float rd = 1.0f / fmaxf((float)(end - beg), 1.0f);
    acc.x *= rd; acc.y *= rd; acc.z *= rd; acc.w *= rd;
    *(float4*)(g_agg + gw * FD + lane * 4) = acc;
}

// ============================================================================
// SAGE linear: R5 micro-kernel; contiguous balanced row partition per block.
// ============================================================================
template <bool RELU>
__global__ void __launch_bounds__(512, 1)
sage_linear_kernel(const float* __restrict__ x,
                   const float* __restrict__ Ws,
                   const float* __restrict__ Wn,
                   const float* __restrict__ b,
                   float* __restrict__ out,
                   int rpb)
{
    extern __shared__ float sm[];
    float* smW   = sm;                 // [256][128]
    float* stage = sm + 256 * 128;     // [16][8][128]

    int tid  = threadIdx.x;
    int lane = tid & 31;
    int warp = tid >> 5;

    for (int i = tid; i < (128 * 128) / 4; i += blockDim.x) {
        ((float4*)smW)[i]               = ((const float4*)Ws)[i];
        ((float4*)(smW + 128 * 128))[i] = ((const float4*)Wn)[i];
    }
    __syncthreads();

    int bstart = blockIdx.x * rpb;
    int bend   = min(bstart + rpb, NN);

    float4 bias = *(const float4*)(b + lane * 4);
    float* myStage = stage + warp * (8 * 128);

    for (int base = bstart + warp * 8; base < bend; base += 128) {

        u64 acc[8][2];
#pragma unroll
        for (int r = 0; r < 8; r++) { acc[r][0] = 0ull; acc[r][1] = 0ull; }

#pragma unroll 1
        for (int h = 0; h < 2; h++) {
#pragma unroll
            for (int r = 0; r < 8; r++) {
                int row = base + r;
                float4 v = make_float4(0.f, 0.f, 0.f, 0.f);
                if (row < bend) {
                    const float* p = (h == 0) ? x : (const float*)g_agg;
                    v = *(const float4*)(p + row * FD + lane * 4);
                }
                *(float4*)(myStage + r * 128 + lane * 4) = v;
            }
            __syncwarp();

            const float* wbase = smW + h * 128 * 128;
#pragma unroll 1
            for (int k = 0; k < 128; k += 4) {
                float4 xq[8];
#pragma unroll
                for (int r = 0; r < 8; r++)
                    xq[r] = *(const float4*)(myStage + r * 128 + k);
#pragma unroll
                for (int kk = 0; kk < 4; kk++) {
                    ulonglong2 w = *(const ulonglong2*)(wbase + (k + kk) * 128 + lane * 4);
#pragma unroll
                    for (int r = 0; r < 8; r++) {
                        float xs = (kk == 0) ? xq[r].x : (kk == 1) ? xq[r].y
                                 : (kk == 2) ? xq[r].z : xq[r].w;
                        u64 xx = pack_dup(xs);
                        ffma2(acc[r][0], xx, w.x);
                        ffma2(acc[r][1], xx, w.y);
                    }
                }
            }
            __syncwarp();
        }

#pragma unroll
        for (int r = 0; r < 8; r++) {
            int row = base + r;
            if (row < bend) {
                float4 o;
                unpack2(o.x, o.y, acc[r][0]);
                unpack2(o.z, o.w, acc[r][1]);
                o.x += bias.x; o.y += bias.y; o.z += bias.z; o.w += bias.w;
                if (RELU) {
                    o.x = fmaxf(o.x, 0.f); o.y = fmaxf(o.y, 0.f);
                    o.z = fmaxf(o.z, 0.f); o.w = fmaxf(o.w, 0.f);
                }
                *(float4*)(out + row * FD + lane * 4) = o;
            }
        }
    }
}

// ============================================================================
// Fused decoder: R5 micro-kernel; contiguous balanced row partition per block.
// ============================================================================
__global__ void __launch_bounds__(512, 1)
decoder_kernel(const float* __restrict__ h,
               const int* __restrict__ ps, const int* __restrict__ pd,
               const int* __restrict__ ns, const int* __restrict__ nd,
               const float* __restrict__ Wd1, const float* __restrict__ bd1,
               const float* __restrict__ Wd2, const float* __restrict__ bd2,
               const float* __restrict__ Wd3, const float* __restrict__ bd3,
               float* __restrict__ out,
               int rpb)
{
    extern __shared__ float sm[];
    float* smW1  = sm;                 // [128][128]
    float* smW2  = sm + 128 * 128;     // [128][128]
    float* stage = sm + 2 * 128 * 128; // [16][8][128]

    int tid  = threadIdx.x;
    int lane = tid & 31;
    int warp = tid >> 5;

    for (int i = tid; i < (128 * 128) / 4; i += blockDim.x) {
        ((float4*)smW1)[i] = ((const float4*)Wd1)[i];
        ((float4*)smW2)[i] = ((const float4*)Wd2)[i];
    }
    __syncthreads();

    float4 b1v = *(const float4*)(bd1 + lane * 4);
    float4 b2v = *(const float4*)(bd2 + lane * 4);
    float4 w3v = *(const float4*)(Wd3 + lane * 4);
    float  b3  = bd3[0];

    float* myStage = stage + warp * (8 * 128);
    const int total = 2 * PP;

    int bstart = blockIdx.x * rpb;
    int bend   = min(bstart + rpb, total);

    for (int base = bstart + warp * 8; base < bend; base += 128) {
        // ---- stage z = h[s] * h[d] ----
#pragma unroll
        for (int r = 0; r < 8; r++) {
            int p = base + r;
            float4 z = make_float4(0.f, 0.f, 0.f, 0.f);
            if (p < bend) {
                int s, d;
                if (p < PP) { s = ps[p]; d = pd[p]; }
                else        { s = ns[p - PP]; d = nd[p - PP]; }
                float4 a = *(const float4*)(h + s * FD + lane * 4);
                float4 c = *(const float4*)(h + d * FD + lane * 4);
                z.x = a.x * c.x; z.y = a.y * c.y;
                z.z = a.z * c.z; z.w = a.w * c.w;
            }
            *(float4*)(myStage + r * 128 + lane * 4) = z;
        }
        __syncwarp();

        u64 acc[8][2];

        // ---- GEMV 1 ----
#pragma unroll
        for (int r = 0; r < 8; r++) { acc[r][0] = 0ull; acc[r][1] = 0ull; }
#pragma unroll 1
        for (int k = 0; k < 128; k += 4) {
            float4 zq[8];
#pragma unroll
            for (int r = 0; r < 8; r++)
                zq[r] = *(const float4*)(myStage + r * 128 + k);
#pragma unroll
            for (int kk = 0; kk < 4; kk++) {
                ulonglong2 w = *(const ulonglong2*)(smW1 + (k + kk) * 128 + lane * 4);
#pragma unroll
                for (int r = 0; r < 8; r++) {
                    float zs = (kk == 0) ? zq[r].x : (kk == 1) ? zq[r].y
                             : (kk == 2) ? zq[r].z : zq[r].w;
                    u64 zz = pack_dup(zs);
                    ffma2(acc[r][0], zz, w.x);
                    ffma2(acc[r][1], zz, w.y);
                }
            }
        }
        __syncwarp();

        // ---- t1 = relu(acc + b1) -> restage (warp-local) ----
#pragma unroll
        for (int r = 0; r < 8; r++) {
            float lo0, hi0, lo1, hi1;
            unpack2(lo0, hi0, acc[r][0]);
            unpack2(lo1, hi1, acc[r][1]);
            float4 tq;
            tq.x = fmaxf(lo0 + b1v.x, 0.f);
            tq.y = fmaxf(hi0 + b1v.y, 0.f);
            tq.z = fmaxf(lo1 + b1v.z, 0.f);
            tq.w = fmaxf(hi1 + b1v.w, 0.f);
            *(float4*)(myStage + r * 128 + lane * 4) = tq;
        }
        __syncwarp();

        // ---- GEMV 2 ----
#pragma unroll
        for (int r = 0; r < 8; r++) { acc[r][0] = 0ull; acc[r][1] = 0ull; }
#pragma unroll 1
        for (int k = 0; k < 128; k += 4) {
            float4 zq[8];
#pragma unroll
            for (int r = 0; r < 8; r++)
                zq[r] = *(const float4*)(myStage + r * 128 + k);
#pragma unroll
            for (int kk = 0; kk < 4; kk++) {
                ulonglong2 w = *(const ulonglong2*)(smW2 + (k + kk) * 128 + lane * 4);
#pragma unroll
                for (int r = 0; r < 8; r++) {
                    float zs = (kk == 0) ? zq[r].x : (kk == 1) ? zq[r].y
                             : (kk == 2) ? zq[r].z : zq[r].w;
                    u64 zz = pack_dup(zs);
                    ffma2(acc[r][0], zz, w.x);
                    ffma2(acc[r][1], zz, w.y);
                }
            }
        }

        // ---- out = relu(acc + b2) . Wd3 + bd3 ----
#pragma unroll
        for (int r = 0; r < 8; r++) {
            float t0, t1, t2, t3;
            unpack2(t0, t1, acc[r][0]);
            unpack2(t2, t3, acc[r][1]);
            t0 = fmaxf(t0 + b2v.x, 0.f);
            t1 = fmaxf(t1 + b2v.y, 0.f);
            t2 = fmaxf(t2 + b2v.z, 0.f);
            t3 = fmaxf(t3 + b2v.w, 0.f);
            float partial = t0 * w3v.x + t1 * w3v.y + t2 * w3v.z + t3 * w3v.w;
#pragma unroll
            for (int off = 16; off > 0; off >>= 1)
                partial += __shfl_xor_sync(0xffffffffu, partial, off);
            int p = base + r;
            if (lane == 0 && p < bend) out[p] = partial + b3;
        }
        __syncwarp();
    }
}

// ============================================================================
// launch
// ============================================================================
extern "C" void kernel_launch(void* const* d_in, const int* in_sizes, int n_in,
                              void* d_out, int out_size)
{
    const float* x    = (const float*)d_in[0];
    const int*   esrc = (const int*)  d_in[1];
    const int*   edst = (const int*)  d_in[2];
    const int*   ps   = (const int*)  d_in[3];
    const int*   pd   = (const int*)  d_in[4];
    const int*   ns   = (const int*)  d_in[5];
    const int*   nd   = (const int*)  d_in[6];
    const float* Ws1  = (const float*)d_in[7];
    const float* Wn1  = (const float*)d_in[8];
    const float* b1   = (const float*)d_in[9];
    const float* Ws2  = (const float*)d_in[10];
    const float* Wn2  = (const float*)d_in[11];
    const float* b2   = (const float*)d_in[12];
    const float* Wd1  = (const float*)d_in[13];
    const float* bd1  = (const float*)d_in[14];
    const float* Wd2  = (const float*)d_in[15];
    const float* bd2  = (const float*)d_in[16];
    const float* Wd3  = (const float*)d_in[17];
    const float* bd3  = (const float*)d_in[18];
    float* out = (float*)d_out;

    void *cntPtr, *curPtr, *h1Ptr, *h2Ptr;
    cudaGetSymbolAddress(&cntPtr, g_cnt);
    cudaGetSymbolAddress(&curPtr, g_cur);
    cudaGetSymbolAddress(&h1Ptr,  g_h1);
    cudaGetSymbolAddress(&h2Ptr,  g_h2);

    int nsm = 148;
    cudaDeviceGetAttribute(&nsm, cudaDevAttrMultiProcessorCount, 0);

    // balanced contiguous partitions (rounded up to multiple of 8)
    int rpb_sage = (((NN + nsm - 1) / nsm) + 7) & ~7;
    int rpb_dec  = (((2 * PP + nsm - 1) / nsm) + 7) & ~7;

    const int SAGE_SMEM = 256 * 128 * 4 + 16 * 8 * 128 * 4;       // 196608 B
    const int DEC_SMEM  = 2 * 128 * 128 * 4 + 16 * 8 * 128 * 4;   // 196608 B
    cudaFuncSetAttribute(sage_linear_kernel<true>,
                         cudaFuncAttributeMaxDynamicSharedMemorySize, SAGE_SMEM);
    cudaFuncSetAttribute(sage_linear_kernel<false>,
                         cudaFuncAttributeMaxDynamicSharedMemorySize, SAGE_SMEM);
    cudaFuncSetAttribute(decoder_kernel,
                         cudaFuncAttributeMaxDynamicSharedMemorySize, DEC_SMEM);

    // ---- CSR build ----
    cudaMemsetAsync(cntPtr, 0, sizeof(int) * NN, 0);
    cudaMemsetAsync(curPtr, 0, sizeof(int) * NN, 0);
    count_kernel<<<(EE + 255) / 256, 256>>>(edst);
    scan_kernel<<<1, 1024>>>();
    fill_kernel<<<(EE + 255) / 256, 256>>>(esrc, edst);

    int ablocks = (NN * 32 + 255) / 256;

    // ---- layer 1 ----
    aggregate_kernel<<<ablocks, 256>>>(x);
    sage_linear_kernel<true><<<nsm, 512, SAGE_SMEM>>>(x, Ws1, Wn1, b1,
                                                      (float*)h1Ptr, rpb_sage);
    // ---- layer 2 ----
    aggregate_kernel<<<ablocks, 256>>>((const float*)h1Ptr);
    sage_linear_kernel<false><<<nsm, 512, SAGE_SMEM>>>((const float*)h1Ptr,
                                                       Ws2, Wn2, b2,
                                                       (float*)h2Ptr, rpb_sage);
    // ---- decoder ----
    decoder_kernel<<<nsm, 512, DEC_SMEM>>>((const float*)h2Ptr,
                                           ps, pd, ns, nd,
                                           Wd1, bd1, Wd2, bd2, Wd3, bd3, out,
                                           rpb_dec);
}